// round 15
// baseline (speedup 1.0000x reference)
#include <cuda_runtime.h>
#include <cuda_fp16.h>

#define TT 32768      // B*S tokens
#define SS 8192       // sequence length
#define DD 512        // model dim
#define FF 2048       // ffn hidden
#define NMOE 1024     // concatenated MoE hidden (2 layers * E*H)
#define NUP (FF + NMOE)   // 3072 fused up-projection width

#define BM 128
#define BN 128
#define BK 64                              // halves per K-chunk (128B rows)
#define NSTG 3
#define ROWB 128                           // bytes per smem row
#define STG_BYTES ((BM + BN) * ROWB)       // 32768
#define SMEM_BYTES (NSTG * STG_BYTES)      // 98304

#define NT_UP   (24 * 256)                 // up-GEMM tiles
#define NT_DOWN (4 * 256)                  // down-GEMM tiles
#define NPERS   304                        // persistent CTAs (2 x 152 SMs)

// Scratch (device globals; no allocation allowed)
__device__ __half g_H[(unsigned long long)TT * NUP];   // [H1 | Hm] fused hidden
__device__ __half g_Xc[(unsigned long long)TT * DD];   // fp16 x
__device__ __half g_Wu[NUP * DD];    // stacked up weights   [3072,512] K-major
__device__ __half g_Wd[DD * NUP];    // stacked down weights [512,3072] K-major
__device__ float  g_w[TT * 16];      // dense gate weights
__device__ unsigned g_ctr_up;        // tile queues (reset in gate_kernel)
__device__ unsigned g_ctr_dn;

__device__ __forceinline__ float gelu_f(float x) {
    float x3 = x * x * x;
    float t = tanhf(0.7978845608028654f * (x + 0.044715f * x3));
    return 0.5f * x * (1.0f + t);
}
__device__ __forceinline__ void cp16(unsigned dst, const void* src) {
    asm volatile("cp.async.cg.shared.global [%0], [%1], 16;" :: "r"(dst), "l"(src) : "memory");
}
__device__ __forceinline__ void ldsm4(unsigned& r0, unsigned& r1, unsigned& r2, unsigned& r3,
                                      unsigned addr) {
    asm volatile("ldmatrix.sync.aligned.m8n8.x4.shared.b16 {%0,%1,%2,%3}, [%4];"
                 : "=r"(r0), "=r"(r1), "=r"(r2), "=r"(r3) : "r"(addr));
}
__device__ __forceinline__ void mma_f16(float* c, const unsigned* a, const unsigned* b) {
    asm volatile(
        "mma.sync.aligned.m16n8k16.row.col.f32.f16.f16.f32 "
        "{%0,%1,%2,%3}, {%4,%5,%6,%7}, {%8,%9}, {%0,%1,%2,%3};"
        : "+f"(c[0]), "+f"(c[1]), "+f"(c[2]), "+f"(c[3])
        : "r"(a[0]), "r"(a[1]), "r"(a[2]), "r"(a[3]), "r"(b[0]), "r"(b[1]));
}

// ---------------------------------------------------------------------------
// Prep: stacked weight repacks (K-major fp16)
// ---------------------------------------------------------------------------
__global__ void prep_wu(const float* __restrict__ W1,
                        const float* __restrict__ Wa1, const float* __restrict__ Wa2) {
    int i = blockIdx.x * 256 + threadIdx.x;       // 0 .. 3072*512-1
    int n = i >> 9, d = i & 511;
    float v;
    if (n < FF) {
        v = W1[d * FF + n];
    } else {
        int c = n - FF;                            // 0..1023
        const float* Wa = (c >> 9) ? Wa2 : Wa1;    // [E,D,H]
        int cc = c & 511;
        v = Wa[((cc >> 6) * DD + d) * 64 + (cc & 63)];
    }
    g_Wu[i] = __float2half_rn(v);
}
__global__ void prep_wd(const float* __restrict__ W2,
                        const float* __restrict__ Wb1, const float* __restrict__ Wb2) {
    int i = blockIdx.x * 256 + threadIdx.x;       // 0 .. 512*3072-1
    int d = i / NUP, k = i % NUP;
    float v;
    if (k < FF) {
        v = W2[k * DD + d];
    } else {
        int j = k - FF;                            // 0..1023
        const float* Wb = (j >> 9) ? Wb2 : Wb1;    // flat [512,512]
        v = Wb[(j & 511) * DD + d];
    }
    g_Wd[i] = __float2half_rn(v);
}

// ---------------------------------------------------------------------------
// Gating v3: 4 tokens per warp, fused x->fp16 conversion.
// Also resets the persistent-GEMM tile counters (runs before both GEMMs
// in stream order on every graph replay -> deterministic).
// ---------------------------------------------------------------------------
__device__ __forceinline__ void write_top2(const float* a, float* o) {
    int i0 = 0; float v0 = a[0];
#pragma unroll
    for (int e = 1; e < 8; e++) if (a[e] > v0) { v0 = a[e]; i0 = e; }
    int i1 = -1; float v1 = -3.4e38f;
#pragma unroll
    for (int e = 0; e < 8; e++) if (e != i0 && a[e] > v1) { v1 = a[e]; i1 = e; }
    float t = expf(v1 - v0);
    float inv = 1.0f / (1.0f + t);
#pragma unroll
    for (int e = 0; e < 8; e++) o[e] = 0.0f;
    o[i0] = inv;
    o[i1] = t * inv;
}

__global__ __launch_bounds__(256)
void gate_kernel(const float* __restrict__ x,
                 const float* __restrict__ Wg1,
                 const float* __restrict__ Wg2) {
    __shared__ float Wg_s[DD * 20];                 // [j][0..15], stride 20 (40KB)
    const int tid  = threadIdx.x;
    const int wid  = tid >> 5;
    const int lane = tid & 31;

    if (blockIdx.x == 0 && tid == 0) { g_ctr_up = 0; g_ctr_dn = 0; }

#pragma unroll
    for (int i = 0; i < 8; i++) {
        int v = tid + i * 256;                      // 0..2047
        int layer = v >> 10, rem = v & 1023;
        int j = rem >> 1, e4 = rem & 1;
        float4 w = ((const float4*)(layer ? Wg2 : Wg1))[(size_t)j * 2 + e4];
        *(float4*)&Wg_s[j * 20 + layer * 8 + e4 * 4] = w;
    }
    __syncthreads();

    const int tok0 = blockIdx.x * 32 + wid * 4;

    float acc[4][16];
#pragma unroll
    for (int p = 0; p < 4; p++)
#pragma unroll
        for (int e = 0; e < 16; e++) acc[p][e] = 0.0f;

#pragma unroll
    for (int q = 0; q < 16; q++) {
        int j = q * 32 + lane;
        const float4* wrow = (const float4*)&Wg_s[j * 20];
        float4 w0 = wrow[0], w1 = wrow[1], w2 = wrow[2], w3 = wrow[3];
        float wv[16] = { w0.x, w0.y, w0.z, w0.w, w1.x, w1.y, w1.z, w1.w,
                         w2.x, w2.y, w2.z, w2.w, w3.x, w3.y, w3.z, w3.w };
#pragma unroll
        for (int p = 0; p < 4; p++) {
            float xv = x[(size_t)(tok0 + p) * DD + j];          // coalesced
            g_Xc[(size_t)(tok0 + p) * DD + j] = __float2half_rn(xv);
#pragma unroll
            for (int e = 0; e < 16; e++)
                acc[p][e] = fmaf(xv, wv[e], acc[p][e]);
        }
    }

#pragma unroll
    for (int p = 0; p < 4; p++)
#pragma unroll
        for (int e = 0; e < 16; e++)
#pragma unroll
            for (int o = 16; o; o >>= 1)
                acc[p][e] += __shfl_xor_sync(0xffffffffu, acc[p][e], o);

#pragma unroll
    for (int p = 0; p < 4; p++) {
        if (lane == p) {
            write_top2(acc[p],     &g_w[(tok0 + p) * 16]);
            write_top2(acc[p] + 8, &g_w[(tok0 + p) * 16 + 8]);
        }
    }
}

// ===========================================================================
// GEMM core v5 (unchanged): 256 thr, 8 warps of 64x32, 3-stage cp.async,
// one barrier/K-iter, B-fragment double buffering.
// ===========================================================================
struct Frag { float acc[4][4][4]; };

template <int LDA, int LDB>
__device__ __forceinline__ void gemm_core(
    Frag& F, unsigned smb, int tid, int lane, int m0, int n0, int KT,
    const __half* __restrict__ A0,   // A + row0*LDA
    const __half* __restrict__ B0)   // Bt + col0*LDB
{
    const int r0 = tid >> 3;                    // 0..31
    const int c  = tid & 7;                     // 16B chunk in 128B row
    const __half* pA = A0 + (size_t)r0 * LDA + c * 8;
    const __half* pB = B0 + (size_t)r0 * LDB + c * 8;
    const unsigned dstoff = (unsigned)(r0 * ROWB + ((c ^ (r0 & 7)) << 4));

    auto load_stage = [&](unsigned stbase, int k0) {
        unsigned base = smb + stbase + dstoff;
#pragma unroll
        for (int i = 0; i < 4; i++)                       // A rows r0+32i
            cp16(base + i * 4096, pA + k0 + i * 32 * LDA);
#pragma unroll
        for (int i = 0; i < 4; i++)                       // B rows r0+32i
            cp16(base + BM * ROWB + i * 4096, pB + k0 + i * 32 * LDB);
        asm volatile("cp.async.commit_group;" ::: "memory");
    };

    const unsigned arow = (unsigned)((m0 + (lane & 15)) * ROWB);
    const unsigned brow = (unsigned)((BM + n0 + (lane & 15)) * ROWB);
    unsigned koff[4];
#pragma unroll
    for (int ks = 0; ks < 4; ks++)
        koff[ks] = (unsigned)((((ks * 2 + (lane >> 4)) ^ (lane & 7))) << 4);

    load_stage(0, 0);
    load_stage(STG_BYTES, BK);
    unsigned stC = 0;                  // compute stage byte offset
    unsigned stL = 2 * STG_BYTES;      // next load stage byte offset

#pragma unroll 1
    for (int kt = 0; kt < KT; kt++) {
        if (kt + 1 < KT) {
            asm volatile("cp.async.wait_group 1;" ::: "memory");
        } else {
            asm volatile("cp.async.wait_group 0;" ::: "memory");
        }
        __syncthreads();                       // single barrier per K-iter
        if (kt + 2 < KT) {
            load_stage(stL, (kt + 2) * BK);
            stL += STG_BYTES; if (stL == NSTG * STG_BYTES) stL = 0;
        }

        const unsigned abase = smb + stC + arow;
        const unsigned bbase = smb + stC + brow;
        stC += STG_BYTES; if (stC == NSTG * STG_BYTES) stC = 0;

        unsigned bc[4][2];
        {
            unsigned q0, q1, q2, q3;
            ldsm4(q0, q1, q2, q3, bbase + koff[0]);
            bc[0][0] = q0; bc[0][1] = q2; bc[1][0] = q1; bc[1][1] = q3;
            ldsm4(q0, q1, q2, q3, bbase + koff[0] + 16 * ROWB);
            bc[2][0] = q0; bc[2][1] = q2; bc[3][0] = q1; bc[3][1] = q3;
        }

#pragma unroll
        for (int ks = 0; ks < 4; ks++) {
            unsigned a[4][4];
#pragma unroll
            for (int mt = 0; mt < 4; mt++)
                ldsm4(a[mt][0], a[mt][1], a[mt][2], a[mt][3],
                      abase + koff[ks] + (unsigned)(mt * 16 * ROWB));
            unsigned bn[4][2];
            if (ks < 3) {
                unsigned q0, q1, q2, q3;
                ldsm4(q0, q1, q2, q3, bbase + koff[ks + 1]);
                bn[0][0] = q0; bn[0][1] = q2; bn[1][0] = q1; bn[1][1] = q3;
                ldsm4(q0, q1, q2, q3, bbase + koff[ks + 1] + 16 * ROWB);
                bn[2][0] = q0; bn[2][1] = q2; bn[3][0] = q1; bn[3][1] = q3;
            }
#pragma unroll
            for (int mt = 0; mt < 4; mt++)
#pragma unroll
                for (int nt = 0; nt < 4; nt++)
                    mma_f16(F.acc[mt][nt], a[mt], bc[nt]);
            if (ks < 3) {
#pragma unroll
                for (int nt = 0; nt < 4; nt++) {
                    bc[nt][0] = bn[nt][0]; bc[nt][1] = bn[nt][1];
                }
            }
        }
    }
}

// ---------------------------------------------------------------------------
// Persistent fused up-GEMM: work-stealing over 24x256 tiles.
// g_H[:, :3072] = { gelu(x@W1+b1) | mask*w*gelu(x@Wa) }
// ---------------------------------------------------------------------------
__global__ __launch_bounds__(256, 2)
void gemm_up(const __half* __restrict__ A, const float* __restrict__ b1,
             const int* __restrict__ idp)
{
    extern __shared__ __half sm[];
    const unsigned smb = (unsigned)__cvta_generic_to_shared(sm);
    const int tid = threadIdx.x, wid = tid >> 5, lane = tid & 31;
    const int m0 = (wid >> 2) * 64, n0 = (wid & 3) * 32;
    const int idv = *idp;
    __shared__ unsigned s_tile;

    for (;;) {
        if (tid == 0) s_tile = atomicAdd(&g_ctr_up, 1u);
        __syncthreads();                       // also fences smem reuse
        const unsigned t = s_tile;
        if (t >= NT_UP) break;
        const int col0 = (int)(t % 24) * BN;
        const int row0 = (int)(t / 24) * BM;
        const bool moe = (col0 >= FF);
        if (moe && (row0 & (SS - 1)) + BM - 1 < idv) continue;   // fully masked

        Frag F;
#pragma unroll
        for (int i = 0; i < 4; i++)
#pragma unroll
            for (int j = 0; j < 4; j++)
#pragma unroll
                for (int r = 0; r < 4; r++) F.acc[i][j][r] = 0.0f;

        gemm_core<DD, DD>(F, smb, tid, lane, m0, n0, DD / BK,
                          A + (size_t)row0 * DD, g_Wu + (size_t)col0 * DD);

        const int g = lane >> 2, tt = lane & 3;
#pragma unroll
        for (int mt = 0; mt < 4; mt++) {
#pragma unroll
            for (int nt = 0; nt < 4; nt++) {
                int r0 = row0 + m0 + mt * 16 + g;
                int r1 = r0 + 8;
                int c  = col0 + n0 + nt * 8 + 2 * tt;
                float v00 = F.acc[mt][nt][0], v01 = F.acc[mt][nt][1];
                float v10 = F.acc[mt][nt][2], v11 = F.acc[mt][nt][3];
                __half2 o0, o1;
                if (!moe) {
                    float2 bb = *(const float2*)(b1 + c);
                    o0 = { __float2half_rn(gelu_f(v00 + bb.x)), __float2half_rn(gelu_f(v01 + bb.y)) };
                    o1 = { __float2half_rn(gelu_f(v10 + bb.x)), __float2half_rn(gelu_f(v11 + bb.y)) };
                } else {
                    bool a0 = ((r0 & (SS - 1)) >= idv);
                    bool a1 = ((r1 & (SS - 1)) >= idv);
                    int e = (c - FF) >> 6;                 // 0..15
                    float w0 = a0 ? g_w[r0 * 16 + e] : 0.0f;
                    float w1 = a1 ? g_w[r1 * 16 + e] : 0.0f;
                    o0 = { __float2half_rn(a0 ? gelu_f(v00) * w0 : 0.0f),
                           __float2half_rn(a0 ? gelu_f(v01) * w0 : 0.0f) };
                    o1 = { __float2half_rn(a1 ? gelu_f(v10) * w1 : 0.0f),
                           __float2half_rn(a1 ? gelu_f(v11) * w1 : 0.0f) };
                }
                *(__half2*)(g_H + (size_t)r0 * NUP + c) = o0;
                *(__half2*)(g_H + (size_t)r1 * NUP + c) = o1;
            }
        }
    }
}

// ---------------------------------------------------------------------------
// Persistent fused down-GEMM: work-stealing over 4x256 tiles.
// out = g_H @ [W2t;Wbt]^T + b2. Masked row tiles K=2048; others K=3072.
// ---------------------------------------------------------------------------
__global__ __launch_bounds__(256, 2)
void gemm_down(const float* __restrict__ b2, float* __restrict__ out,
               const int* __restrict__ idp)
{
    extern __shared__ __half sm[];
    const unsigned smb = (unsigned)__cvta_generic_to_shared(sm);
    const int tid = threadIdx.x, wid = tid >> 5, lane = tid & 31;
    const int m0 = (wid >> 2) * 64, n0 = (wid & 3) * 32;
    const int idv = *idp;
    __shared__ unsigned s_tile;

    for (;;) {
        if (tid == 0) s_tile = atomicAdd(&g_ctr_dn, 1u);
        __syncthreads();
        const unsigned t = s_tile;
        if (t >= NT_DOWN) break;
        const int col0 = (int)(t & 3) * BN;
        const int row0 = (int)(t >> 2) * BM;
        const bool fully_masked = ((row0 & (SS - 1)) + BM - 1 < idv);
        const int KT = (fully_masked ? FF : NUP) / BK;

        Frag F;
#pragma unroll
        for (int i = 0; i < 4; i++)
#pragma unroll
            for (int j = 0; j < 4; j++)
#pragma unroll
                for (int r = 0; r < 4; r++) F.acc[i][j][r] = 0.0f;

        gemm_core<NUP, NUP>(F, smb, tid, lane, m0, n0, KT,
                            g_H + (size_t)row0 * NUP, g_Wd + (size_t)col0 * NUP);

        const int g = lane >> 2, tt = lane & 3;
#pragma unroll
        for (int mt = 0; mt < 4; mt++) {
#pragma unroll
            for (int nt = 0; nt < 4; nt++) {
                int r0 = row0 + m0 + mt * 16 + g;
                int r1 = r0 + 8;
                int c  = col0 + n0 + nt * 8 + 2 * tt;
                float2 bb = *(const float2*)(b2 + c);
                float2 o0 = { F.acc[mt][nt][0] + bb.x, F.acc[mt][nt][1] + bb.y };
                float2 o1 = { F.acc[mt][nt][2] + bb.x, F.acc[mt][nt][3] + bb.y };
                *(float2*)(out + (size_t)r0 * DD + c) = o0;
                *(float2*)(out + (size_t)r1 * DD + c) = o1;
            }
        }
    }
}

// ---------------------------------------------------------------------------
extern "C" void kernel_launch(void* const* d_in, const int* in_sizes, int n_in,
                              void* d_out, int out_size) {
    const float* x   = (const float*)d_in[0];
    const int*   idp = (const int*)  d_in[1];
    const float* W1  = (const float*)d_in[2];
    const float* b1  = (const float*)d_in[3];
    const float* W2  = (const float*)d_in[4];
    const float* b2  = (const float*)d_in[5];
    const float* Wg1 = (const float*)d_in[6];
    const float* Wa1 = (const float*)d_in[7];
    const float* Wb1 = (const float*)d_in[8];
    const float* Wg2 = (const float*)d_in[9];
    const float* Wa2 = (const float*)d_in[10];
    const float* Wb2 = (const float*)d_in[11];
    float* out = (float*)d_out;
    (void)in_sizes; (void)n_in; (void)out_size;

    __half* Xc;
    cudaGetSymbolAddress((void**)&Xc, g_Xc);

    cudaFuncSetAttribute(gemm_up,   cudaFuncAttributeMaxDynamicSharedMemorySize, SMEM_BYTES);
    cudaFuncSetAttribute(gemm_down, cudaFuncAttributeMaxDynamicSharedMemorySize, SMEM_BYTES);

    // Prep: stacked repacks + gating (gate also emits fp16 x + resets queues)
    prep_wu<<<NUP * DD / 256, 256>>>(W1, Wa1, Wa2);
    prep_wd<<<DD * NUP / 256, 256>>>(W2, Wb1, Wb2);
    gate_kernel<<<TT / 32, 256>>>(x, Wg1, Wg2);

    // Persistent fused up-projection (FFN1 + both MoE up layers)
    gemm_up<<<NPERS, 256, SMEM_BYTES>>>(Xc, b1, idp);

    // Persistent fused down-projection (single out write)
    gemm_down<<<NPERS, 256, SMEM_BYTES>>>(b2, out, idp);
}

// round 16
// speedup vs baseline: 1.1810x; 1.1810x over previous
#include <cuda_runtime.h>
#include <cuda_fp16.h>

#define TT 32768      // B*S tokens
#define SS 8192       // sequence length
#define DD 512        // model dim
#define FF 2048       // ffn hidden
#define NMOE 1024     // concatenated MoE hidden (2 layers * E*H)
#define NUP (FF + NMOE)   // 3072 fused up-projection width

#define BM 128
#define BN 128
#define BK 64                              // halves per K-chunk (128B rows)
#define NSTG 3
#define ROWB 128                           // bytes per smem row
#define STG_BYTES ((BM + BN) * ROWB)       // 32768
#define SMEM_BYTES (NSTG * STG_BYTES)      // 98304

#define NB_GATE 1024                       // gate blocks (32 tokens each)
#define NB_WU   (NUP * DD / 256)           // 6144
#define NB_WD   (DD * NUP / 256)           // 6144

// Scratch (device globals; no allocation allowed)
__device__ __half g_H[(unsigned long long)TT * NUP];   // [H1 | Hm] fused hidden
__device__ __half g_Xc[(unsigned long long)TT * DD];   // fp16 x
__device__ __half g_Wu[NUP * DD];    // stacked up weights   [3072,512] K-major
__device__ __half g_Wd[DD * NUP];    // stacked down weights [512,3072] K-major
__device__ float  g_w[TT * 16];      // dense gate weights

__device__ __forceinline__ float gelu_f(float x) {
    float x3 = x * x * x;
    float t = tanhf(0.7978845608028654f * (x + 0.044715f * x3));
    return 0.5f * x * (1.0f + t);
}
__device__ __forceinline__ void cp16(unsigned dst, const void* src) {
    asm volatile("cp.async.cg.shared.global [%0], [%1], 16;" :: "r"(dst), "l"(src) : "memory");
}
__device__ __forceinline__ void ldsm4(unsigned& r0, unsigned& r1, unsigned& r2, unsigned& r3,
                                      unsigned addr) {
    asm volatile("ldmatrix.sync.aligned.m8n8.x4.shared.b16 {%0,%1,%2,%3}, [%4];"
                 : "=r"(r0), "=r"(r1), "=r"(r2), "=r"(r3) : "r"(addr));
}
__device__ __forceinline__ void mma_f16(float* c, const unsigned* a, const unsigned* b) {
    asm volatile(
        "mma.sync.aligned.m16n8k16.row.col.f32.f16.f16.f32 "
        "{%0,%1,%2,%3}, {%4,%5,%6,%7}, {%8,%9}, {%0,%1,%2,%3};"
        : "+f"(c[0]), "+f"(c[1]), "+f"(c[2]), "+f"(c[3])
        : "r"(a[0]), "r"(a[1]), "r"(a[2]), "r"(a[3]), "r"(b[0]), "r"(b[1]));
}

// ---------------------------------------------------------------------------
// Fused prologue: gate (blocks 0..1023, critical path) + weight repacks
// (blocks 1024..13311) in a single launch so repacks overlap gating.
// ---------------------------------------------------------------------------
__device__ __forceinline__ void write_top2(const float* a, float* o) {
    int i0 = 0; float v0 = a[0];
#pragma unroll
    for (int e = 1; e < 8; e++) if (a[e] > v0) { v0 = a[e]; i0 = e; }
    int i1 = -1; float v1 = -3.4e38f;
#pragma unroll
    for (int e = 0; e < 8; e++) if (e != i0 && a[e] > v1) { v1 = a[e]; i1 = e; }
    float t = expf(v1 - v0);
    float inv = 1.0f / (1.0f + t);
#pragma unroll
    for (int e = 0; e < 8; e++) o[e] = 0.0f;
    o[i0] = inv;
    o[i1] = t * inv;
}

__global__ __launch_bounds__(256)
void prologue(const float* __restrict__ x,
              const float* __restrict__ Wg1, const float* __restrict__ Wg2,
              const float* __restrict__ W1,
              const float* __restrict__ Wa1, const float* __restrict__ Wa2,
              const float* __restrict__ W2,
              const float* __restrict__ Wb1, const float* __restrict__ Wb2) {
    const int tid = threadIdx.x;
    const int bx  = blockIdx.x;

    if (bx >= NB_GATE) {
        int pb = bx - NB_GATE;
        if (pb < NB_WU) {
            // ---- prep_wu: g_Wu [3072,512] K-major fp16 ----
            int i = pb * 256 + tid;
            int n = i >> 9, d = i & 511;
            float v;
            if (n < FF) {
                v = W1[d * FF + n];
            } else {
                int c = n - FF;
                const float* Wa = (c >> 9) ? Wa2 : Wa1;
                int cc = c & 511;
                v = Wa[((cc >> 6) * DD + d) * 64 + (cc & 63)];
            }
            g_Wu[i] = __float2half_rn(v);
        } else {
            // ---- prep_wd: g_Wd [512,3072] K-major fp16 ----
            int i = (pb - NB_WU) * 256 + tid;
            int d = i / NUP, k = i % NUP;
            float v;
            if (k < FF) {
                v = W2[k * DD + d];
            } else {
                int j = k - FF;
                const float* Wb = (j >> 9) ? Wb2 : Wb1;
                v = Wb[(j & 511) * DD + d];
            }
            g_Wd[i] = __float2half_rn(v);
        }
        return;
    }

    // ---- gate: 4 tokens per warp, fused x->fp16 conversion ----
    __shared__ float Wg_s[DD * 20];                 // [j][0..15], stride 20 (40KB)
    const int wid  = tid >> 5;
    const int lane = tid & 31;

#pragma unroll
    for (int i = 0; i < 8; i++) {
        int v = tid + i * 256;                      // 0..2047
        int layer = v >> 10, rem = v & 1023;
        int j = rem >> 1, e4 = rem & 1;
        float4 w = ((const float4*)(layer ? Wg2 : Wg1))[(size_t)j * 2 + e4];
        *(float4*)&Wg_s[j * 20 + layer * 8 + e4 * 4] = w;
    }
    __syncthreads();

    const int tok0 = bx * 32 + wid * 4;

    float acc[4][16];
#pragma unroll
    for (int p = 0; p < 4; p++)
#pragma unroll
        for (int e = 0; e < 16; e++) acc[p][e] = 0.0f;

#pragma unroll
    for (int q = 0; q < 16; q++) {
        int j = q * 32 + lane;
        const float4* wrow = (const float4*)&Wg_s[j * 20];
        float4 w0 = wrow[0], w1 = wrow[1], w2 = wrow[2], w3 = wrow[3];
        float wv[16] = { w0.x, w0.y, w0.z, w0.w, w1.x, w1.y, w1.z, w1.w,
                         w2.x, w2.y, w2.z, w2.w, w3.x, w3.y, w3.z, w3.w };
#pragma unroll
        for (int p = 0; p < 4; p++) {
            float xv = x[(size_t)(tok0 + p) * DD + j];          // coalesced
            g_Xc[(size_t)(tok0 + p) * DD + j] = __float2half_rn(xv);
#pragma unroll
            for (int e = 0; e < 16; e++)
                acc[p][e] = fmaf(xv, wv[e], acc[p][e]);
        }
    }

#pragma unroll
    for (int p = 0; p < 4; p++)
#pragma unroll
        for (int e = 0; e < 16; e++)
#pragma unroll
            for (int o = 16; o; o >>= 1)
                acc[p][e] += __shfl_xor_sync(0xffffffffu, acc[p][e], o);

#pragma unroll
    for (int p = 0; p < 4; p++) {
        if (lane == p) {
            write_top2(acc[p],     &g_w[(tok0 + p) * 16]);
            write_top2(acc[p] + 8, &g_w[(tok0 + p) * 16 + 8]);
        }
    }
}

// ===========================================================================
// GEMM core v5 (R14, best known): 256 thr, 8 warps of 64x32, 3-stage
// cp.async, one barrier/K-iter, B-fragment double buffering, 2 CTAs/SM.
// ===========================================================================
struct Frag { float acc[4][4][4]; };

template <int LDA, int LDB>
__device__ __forceinline__ void gemm_core(
    Frag& F, unsigned smb, int tid, int lane, int m0, int n0, int KT,
    const __half* __restrict__ A0,   // A + row0*LDA
    const __half* __restrict__ B0)   // Bt + col0*LDB
{
    const int r0 = tid >> 3;                    // 0..31
    const int c  = tid & 7;                     // 16B chunk in 128B row
    const __half* pA = A0 + (size_t)r0 * LDA + c * 8;
    const __half* pB = B0 + (size_t)r0 * LDB + c * 8;
    const unsigned dstoff = (unsigned)(r0 * ROWB + ((c ^ (r0 & 7)) << 4));

    auto load_stage = [&](unsigned stbase, int k0) {
        unsigned base = smb + stbase + dstoff;
#pragma unroll
        for (int i = 0; i < 4; i++)                       // A rows r0+32i
            cp16(base + i * 4096, pA + k0 + i * 32 * LDA);
#pragma unroll
        for (int i = 0; i < 4; i++)                       // B rows r0+32i
            cp16(base + BM * ROWB + i * 4096, pB + k0 + i * 32 * LDB);
        asm volatile("cp.async.commit_group;" ::: "memory");
    };

    const unsigned arow = (unsigned)((m0 + (lane & 15)) * ROWB);
    const unsigned brow = (unsigned)((BM + n0 + (lane & 15)) * ROWB);
    unsigned koff[4];
#pragma unroll
    for (int ks = 0; ks < 4; ks++)
        koff[ks] = (unsigned)((((ks * 2 + (lane >> 4)) ^ (lane & 7))) << 4);

    load_stage(0, 0);
    load_stage(STG_BYTES, BK);
    unsigned stC = 0;                  // compute stage byte offset
    unsigned stL = 2 * STG_BYTES;      // next load stage byte offset

#pragma unroll 1
    for (int kt = 0; kt < KT; kt++) {
        if (kt + 1 < KT) {
            asm volatile("cp.async.wait_group 1;" ::: "memory");
        } else {
            asm volatile("cp.async.wait_group 0;" ::: "memory");
        }
        __syncthreads();                       // single barrier per K-iter
        if (kt + 2 < KT) {
            load_stage(stL, (kt + 2) * BK);
            stL += STG_BYTES; if (stL == NSTG * STG_BYTES) stL = 0;
        }

        const unsigned abase = smb + stC + arow;
        const unsigned bbase = smb + stC + brow;
        stC += STG_BYTES; if (stC == NSTG * STG_BYTES) stC = 0;

        unsigned bc[4][2];
        {
            unsigned q0, q1, q2, q3;
            ldsm4(q0, q1, q2, q3, bbase + koff[0]);
            bc[0][0] = q0; bc[0][1] = q2; bc[1][0] = q1; bc[1][1] = q3;
            ldsm4(q0, q1, q2, q3, bbase + koff[0] + 16 * ROWB);
            bc[2][0] = q0; bc[2][1] = q2; bc[3][0] = q1; bc[3][1] = q3;
        }

#pragma unroll
        for (int ks = 0; ks < 4; ks++) {
            unsigned a[4][4];
#pragma unroll
            for (int mt = 0; mt < 4; mt++)
                ldsm4(a[mt][0], a[mt][1], a[mt][2], a[mt][3],
                      abase + koff[ks] + (unsigned)(mt * 16 * ROWB));
            unsigned bn[4][2];
            if (ks < 3) {
                unsigned q0, q1, q2, q3;
                ldsm4(q0, q1, q2, q3, bbase + koff[ks + 1]);
                bn[0][0] = q0; bn[0][1] = q2; bn[1][0] = q1; bn[1][1] = q3;
                ldsm4(q0, q1, q2, q3, bbase + koff[ks + 1] + 16 * ROWB);
                bn[2][0] = q0; bn[2][1] = q2; bn[3][0] = q1; bn[3][1] = q3;
            }
#pragma unroll
            for (int mt = 0; mt < 4; mt++)
#pragma unroll
                for (int nt = 0; nt < 4; nt++)
                    mma_f16(F.acc[mt][nt], a[mt], bc[nt]);
            if (ks < 3) {
#pragma unroll
                for (int nt = 0; nt < 4; nt++) {
                    bc[nt][0] = bn[nt][0]; bc[nt][1] = bn[nt][1];
                }
            }
        }
    }
}

// ---------------------------------------------------------------------------
// Fused up-GEMM: g_H[:, :3072] = { gelu(x@W1+b1) | mask*w*gelu(x@Wa) }
// ---------------------------------------------------------------------------
__global__ __launch_bounds__(256, 2)
void gemm_up(const __half* __restrict__ A, const float* __restrict__ b1,
             const int* __restrict__ idp)
{
    const int col0 = blockIdx.x * BN;
    const int row0 = blockIdx.y * BM;
    const bool moe = (col0 >= FF);
    const int idv = *idp;
    if (moe && (row0 & (SS - 1)) + BM - 1 < idv) return;   // fully masked MoE tile

    extern __shared__ __half sm[];
    const unsigned smb = (unsigned)__cvta_generic_to_shared(sm);
    const int tid = threadIdx.x, wid = tid >> 5, lane = tid & 31;
    const int m0 = (wid >> 2) * 64, n0 = (wid & 3) * 32;

    Frag F;
#pragma unroll
    for (int i = 0; i < 4; i++)
#pragma unroll
        for (int j = 0; j < 4; j++)
#pragma unroll
            for (int r = 0; r < 4; r++) F.acc[i][j][r] = 0.0f;

    gemm_core<DD, DD>(F, smb, tid, lane, m0, n0, DD / BK,
                      A + (size_t)row0 * DD, g_Wu + (size_t)col0 * DD);

    const int g = lane >> 2, t = lane & 3;
#pragma unroll
    for (int mt = 0; mt < 4; mt++) {
#pragma unroll
        for (int nt = 0; nt < 4; nt++) {
            int r0 = row0 + m0 + mt * 16 + g;
            int r1 = r0 + 8;
            int c  = col0 + n0 + nt * 8 + 2 * t;
            float v00 = F.acc[mt][nt][0], v01 = F.acc[mt][nt][1];
            float v10 = F.acc[mt][nt][2], v11 = F.acc[mt][nt][3];
            __half2 o0, o1;
            if (!moe) {
                float2 bb = *(const float2*)(b1 + c);
                o0 = { __float2half_rn(gelu_f(v00 + bb.x)), __float2half_rn(gelu_f(v01 + bb.y)) };
                o1 = { __float2half_rn(gelu_f(v10 + bb.x)), __float2half_rn(gelu_f(v11 + bb.y)) };
            } else {
                bool a0 = ((r0 & (SS - 1)) >= idv);
                bool a1 = ((r1 & (SS - 1)) >= idv);
                int e = (c - FF) >> 6;                 // 0..15
                float w0 = a0 ? g_w[r0 * 16 + e] : 0.0f;
                float w1 = a1 ? g_w[r1 * 16 + e] : 0.0f;
                o0 = { __float2half_rn(a0 ? gelu_f(v00) * w0 : 0.0f),
                       __float2half_rn(a0 ? gelu_f(v01) * w0 : 0.0f) };
                o1 = { __float2half_rn(a1 ? gelu_f(v10) * w1 : 0.0f),
                       __float2half_rn(a1 ? gelu_f(v11) * w1 : 0.0f) };
            }
            *(__half2*)(g_H + (size_t)r0 * NUP + c) = o0;
            *(__half2*)(g_H + (size_t)r1 * NUP + c) = o1;
        }
    }
}

// ---------------------------------------------------------------------------
// Fused down-GEMM: out = g_H @ [W2t;Wbt]^T + b2.
// Fully-masked row tiles use K=2048; others K=3072.
// ---------------------------------------------------------------------------
__global__ __launch_bounds__(256, 2)
void gemm_down(const float* __restrict__ b2, float* __restrict__ out,
               const int* __restrict__ idp)
{
    const int col0 = blockIdx.x * BN;
    const int row0 = blockIdx.y * BM;
    const int idv = *idp;
    const bool fully_masked = ((row0 & (SS - 1)) + BM - 1 < idv);
    const int KT = (fully_masked ? FF : NUP) / BK;

    extern __shared__ __half sm[];
    const unsigned smb = (unsigned)__cvta_generic_to_shared(sm);
    const int tid = threadIdx.x, wid = tid >> 5, lane = tid & 31;
    const int m0 = (wid >> 2) * 64, n0 = (wid & 3) * 32;

    Frag F;
#pragma unroll
    for (int i = 0; i < 4; i++)
#pragma unroll
        for (int j = 0; j < 4; j++)
#pragma unroll
            for (int r = 0; r < 4; r++) F.acc[i][j][r] = 0.0f;

    gemm_core<NUP, NUP>(F, smb, tid, lane, m0, n0, KT,
                        g_H + (size_t)row0 * NUP, g_Wd + (size_t)col0 * NUP);

    const int g = lane >> 2, t = lane & 3;
#pragma unroll
    for (int mt = 0; mt < 4; mt++) {
#pragma unroll
        for (int nt = 0; nt < 4; nt++) {
            int r0 = row0 + m0 + mt * 16 + g;
            int r1 = r0 + 8;
            int c  = col0 + n0 + nt * 8 + 2 * t;
            float2 bb = *(const float2*)(b2 + c);
            float2 o0 = { F.acc[mt][nt][0] + bb.x, F.acc[mt][nt][1] + bb.y };
            float2 o1 = { F.acc[mt][nt][2] + bb.x, F.acc[mt][nt][3] + bb.y };
            *(float2*)(out + (size_t)r0 * DD + c) = o0;
            *(float2*)(out + (size_t)r1 * DD + c) = o1;
        }
    }
}

// ---------------------------------------------------------------------------
extern "C" void kernel_launch(void* const* d_in, const int* in_sizes, int n_in,
                              void* d_out, int out_size) {
    const float* x   = (const float*)d_in[0];
    const int*   idp = (const int*)  d_in[1];
    const float* W1  = (const float*)d_in[2];
    const float* b1  = (const float*)d_in[3];
    const float* W2  = (const float*)d_in[4];
    const float* b2  = (const float*)d_in[5];
    const float* Wg1 = (const float*)d_in[6];
    const float* Wa1 = (const float*)d_in[7];
    const float* Wb1 = (const float*)d_in[8];
    const float* Wg2 = (const float*)d_in[9];
    const float* Wa2 = (const float*)d_in[10];
    const float* Wb2 = (const float*)d_in[11];
    float* out = (float*)d_out;
    (void)in_sizes; (void)n_in; (void)out_size;

    __half* Xc;
    cudaGetSymbolAddress((void**)&Xc, g_Xc);

    cudaFuncSetAttribute(gemm_up,   cudaFuncAttributeMaxDynamicSharedMemorySize, SMEM_BYTES);
    cudaFuncSetAttribute(gemm_down, cudaFuncAttributeMaxDynamicSharedMemorySize, SMEM_BYTES);

    // Fused prologue: gate (first blocks, critical path) + both weight repacks
    prologue<<<NB_GATE + NB_WU + NB_WD, 256>>>(x, Wg1, Wg2, W1, Wa1, Wa2, W2, Wb1, Wb2);

    // Fused up-projection (FFN1 + both MoE up layers)
    gemm_up<<<dim3(NUP / BN, TT / BM), 256, SMEM_BYTES>>>(Xc, b1, idp);

    // Fused down-projection (FFN2 + both MoE down layers, single out write)
    gemm_down<<<dim3(DD / BN, TT / BM), 256, SMEM_BYTES>>>(b2, out, idp);
}

// round 17
// speedup vs baseline: 1.2140x; 1.0280x over previous
#include <cuda_runtime.h>
#include <cuda_fp16.h>

#define TT 32768      // B*S tokens
#define SS 8192       // sequence length
#define DD 512        // model dim
#define FF 2048       // ffn hidden
#define NMOE 1024     // concatenated MoE hidden (2 layers * E*H)
#define NUP (FF + NMOE)   // 3072 fused up-projection width

#define BM 128
#define BN 128
#define BK 64                              // halves per K-chunk (128B rows)
#define NSTG 3
#define ROWB 128                           // bytes per smem row
#define STG_BYTES ((BM + BN) * ROWB)       // 32768
#define SMEM_BYTES (NSTG * STG_BYTES)      // 98304

#define NB_WU (NUP * DD / 256)             // 6144 repack blocks for Wu
#define NB_WD (DD * NUP / 256)             // 6144 repack blocks for Wd

// Scratch (device globals; no allocation allowed)
__device__ __half g_H[(unsigned long long)TT * NUP];   // [H1 | Hm] fused hidden
__device__ __half g_Xc[(unsigned long long)TT * DD];   // fp16 x
__device__ __half g_Wu[NUP * DD];    // stacked up weights   [3072,512] K-major
__device__ __half g_Wd[DD * NUP];    // stacked down weights [512,3072] K-major
__device__ float  g_w[TT * 16];      // dense gate weights

__device__ __forceinline__ float gelu_f(float x) {
    float x3 = x * x * x;
    float t = tanhf(0.7978845608028654f * (x + 0.044715f * x3));
    return 0.5f * x * (1.0f + t);
}
__device__ __forceinline__ void cp16(unsigned dst, const void* src) {
    asm volatile("cp.async.cg.shared.global [%0], [%1], 16;" :: "r"(dst), "l"(src) : "memory");
}
__device__ __forceinline__ void ldsm4(unsigned& r0, unsigned& r1, unsigned& r2, unsigned& r3,
                                      unsigned addr) {
    asm volatile("ldmatrix.sync.aligned.m8n8.x4.shared.b16 {%0,%1,%2,%3}, [%4];"
                 : "=r"(r0), "=r"(r1), "=r"(r2), "=r"(r3) : "r"(addr));
}
__device__ __forceinline__ void mma_f16(float* c, const unsigned* a, const unsigned* b) {
    asm volatile(
        "mma.sync.aligned.m16n8k16.row.col.f32.f16.f16.f32 "
        "{%0,%1,%2,%3}, {%4,%5,%6,%7}, {%8,%9}, {%0,%1,%2,%3};"
        : "+f"(c[0]), "+f"(c[1]), "+f"(c[2]), "+f"(c[3])
        : "r"(a[0]), "r"(a[1]), "r"(a[2]), "r"(a[3]), "r"(b[0]), "r"(b[1]));
}

// ---------------------------------------------------------------------------
// Merged weight repack (both halves are trivial, regs~16, full occupancy):
// blocks [0, NB_WU)       -> g_Wu [3072,512] K-major fp16
// blocks [NB_WU, +NB_WD)  -> g_Wd [512,3072] K-major fp16
// ---------------------------------------------------------------------------
__global__ void prep_w(const float* __restrict__ W1,
                       const float* __restrict__ Wa1, const float* __restrict__ Wa2,
                       const float* __restrict__ W2,
                       const float* __restrict__ Wb1, const float* __restrict__ Wb2) {
    int bx = blockIdx.x;
    if (bx < NB_WU) {
        int i = bx * 256 + threadIdx.x;           // 0 .. 3072*512-1
        int n = i >> 9, d = i & 511;
        float v;
        if (n < FF) {
            v = W1[d * FF + n];
        } else {
            int c = n - FF;                        // 0..1023
            const float* Wa = (c >> 9) ? Wa2 : Wa1;
            int cc = c & 511;
            v = Wa[((cc >> 6) * DD + d) * 64 + (cc & 63)];
        }
        g_Wu[i] = __float2half_rn(v);
    } else {
        int i = (bx - NB_WU) * 256 + threadIdx.x; // 0 .. 512*3072-1
        int d = i / NUP, k = i % NUP;
        float v;
        if (k < FF) {
            v = W2[k * DD + d];
        } else {
            int j = k - FF;                        // 0..1023
            const float* Wb = (j >> 9) ? Wb2 : Wb1;
            v = Wb[(j & 511) * DD + d];
        }
        g_Wd[i] = __float2half_rn(v);
    }
}

// ---------------------------------------------------------------------------
// Gating v3 (R14): 4 tokens per warp, fused x->fp16 conversion.
// ---------------------------------------------------------------------------
__device__ __forceinline__ void write_top2(const float* a, float* o) {
    int i0 = 0; float v0 = a[0];
#pragma unroll
    for (int e = 1; e < 8; e++) if (a[e] > v0) { v0 = a[e]; i0 = e; }
    int i1 = -1; float v1 = -3.4e38f;
#pragma unroll
    for (int e = 0; e < 8; e++) if (e != i0 && a[e] > v1) { v1 = a[e]; i1 = e; }
    float t = expf(v1 - v0);
    float inv = 1.0f / (1.0f + t);
#pragma unroll
    for (int e = 0; e < 8; e++) o[e] = 0.0f;
    o[i0] = inv;
    o[i1] = t * inv;
}

__global__ __launch_bounds__(256)
void gate_kernel(const float* __restrict__ x,
                 const float* __restrict__ Wg1,
                 const float* __restrict__ Wg2) {
    __shared__ float Wg_s[DD * 20];                 // [j][0..15], stride 20 (40KB)
    const int tid  = threadIdx.x;
    const int wid  = tid >> 5;
    const int lane = tid & 31;

#pragma unroll
    for (int i = 0; i < 8; i++) {
        int v = tid + i * 256;                      // 0..2047
        int layer = v >> 10, rem = v & 1023;
        int j = rem >> 1, e4 = rem & 1;
        float4 w = ((const float4*)(layer ? Wg2 : Wg1))[(size_t)j * 2 + e4];
        *(float4*)&Wg_s[j * 20 + layer * 8 + e4 * 4] = w;
    }
    __syncthreads();

    const int tok0 = blockIdx.x * 32 + wid * 4;

    float acc[4][16];
#pragma unroll
    for (int p = 0; p < 4; p++)
#pragma unroll
        for (int e = 0; e < 16; e++) acc[p][e] = 0.0f;

#pragma unroll
    for (int q = 0; q < 16; q++) {
        int j = q * 32 + lane;
        const float4* wrow = (const float4*)&Wg_s[j * 20];
        float4 w0 = wrow[0], w1 = wrow[1], w2 = wrow[2], w3 = wrow[3];
        float wv[16] = { w0.x, w0.y, w0.z, w0.w, w1.x, w1.y, w1.z, w1.w,
                         w2.x, w2.y, w2.z, w2.w, w3.x, w3.y, w3.z, w3.w };
#pragma unroll
        for (int p = 0; p < 4; p++) {
            float xv = x[(size_t)(tok0 + p) * DD + j];          // coalesced
            g_Xc[(size_t)(tok0 + p) * DD + j] = __float2half_rn(xv);
#pragma unroll
            for (int e = 0; e < 16; e++)
                acc[p][e] = fmaf(xv, wv[e], acc[p][e]);
        }
    }

#pragma unroll
    for (int p = 0; p < 4; p++)
#pragma unroll
        for (int e = 0; e < 16; e++)
#pragma unroll
            for (int o = 16; o; o >>= 1)
                acc[p][e] += __shfl_xor_sync(0xffffffffu, acc[p][e], o);

#pragma unroll
    for (int p = 0; p < 4; p++) {
        if (lane == p) {
            write_top2(acc[p],     &g_w[(tok0 + p) * 16]);
            write_top2(acc[p] + 8, &g_w[(tok0 + p) * 16 + 8]);
        }
    }
}

// ===========================================================================
// GEMM core v5 (R14, best known): 256 thr, 8 warps of 64x32, 3-stage
// cp.async, one barrier/K-iter, B-fragment double buffering, 2 CTAs/SM.
// ===========================================================================
struct Frag { float acc[4][4][4]; };

template <int LDA, int LDB>
__device__ __forceinline__ void gemm_core(
    Frag& F, unsigned smb, int tid, int lane, int m0, int n0, int KT,
    const __half* __restrict__ A0,   // A + row0*LDA
    const __half* __restrict__ B0)   // Bt + col0*LDB
{
    const int r0 = tid >> 3;                    // 0..31
    const int c  = tid & 7;                     // 16B chunk in 128B row
    const __half* pA = A0 + (size_t)r0 * LDA + c * 8;
    const __half* pB = B0 + (size_t)r0 * LDB + c * 8;
    const unsigned dstoff = (unsigned)(r0 * ROWB + ((c ^ (r0 & 7)) << 4));

    auto load_stage = [&](unsigned stbase, int k0) {
        unsigned base = smb + stbase + dstoff;
#pragma unroll
        for (int i = 0; i < 4; i++)                       // A rows r0+32i
            cp16(base + i * 4096, pA + k0 + i * 32 * LDA);
#pragma unroll
        for (int i = 0; i < 4; i++)                       // B rows r0+32i
            cp16(base + BM * ROWB + i * 4096, pB + k0 + i * 32 * LDB);
        asm volatile("cp.async.commit_group;" ::: "memory");
    };

    const unsigned arow = (unsigned)((m0 + (lane & 15)) * ROWB);
    const unsigned brow = (unsigned)((BM + n0 + (lane & 15)) * ROWB);
    unsigned koff[4];
#pragma unroll
    for (int ks = 0; ks < 4; ks++)
        koff[ks] = (unsigned)((((ks * 2 + (lane >> 4)) ^ (lane & 7))) << 4);

    load_stage(0, 0);
    load_stage(STG_BYTES, BK);
    unsigned stC = 0;                  // compute stage byte offset
    unsigned stL = 2 * STG_BYTES;      // next load stage byte offset

#pragma unroll 1
    for (int kt = 0; kt < KT; kt++) {
        if (kt + 1 < KT) {
            asm volatile("cp.async.wait_group 1;" ::: "memory");
        } else {
            asm volatile("cp.async.wait_group 0;" ::: "memory");
        }
        __syncthreads();                       // single barrier per K-iter
        if (kt + 2 < KT) {
            load_stage(stL, (kt + 2) * BK);
            stL += STG_BYTES; if (stL == NSTG * STG_BYTES) stL = 0;
        }

        const unsigned abase = smb + stC + arow;
        const unsigned bbase = smb + stC + brow;
        stC += STG_BYTES; if (stC == NSTG * STG_BYTES) stC = 0;

        unsigned bc[4][2];
        {
            unsigned q0, q1, q2, q3;
            ldsm4(q0, q1, q2, q3, bbase + koff[0]);
            bc[0][0] = q0; bc[0][1] = q2; bc[1][0] = q1; bc[1][1] = q3;
            ldsm4(q0, q1, q2, q3, bbase + koff[0] + 16 * ROWB);
            bc[2][0] = q0; bc[2][1] = q2; bc[3][0] = q1; bc[3][1] = q3;
        }

#pragma unroll
        for (int ks = 0; ks < 4; ks++) {
            unsigned a[4][4];
#pragma unroll
            for (int mt = 0; mt < 4; mt++)
                ldsm4(a[mt][0], a[mt][1], a[mt][2], a[mt][3],
                      abase + koff[ks] + (unsigned)(mt * 16 * ROWB));
            unsigned bn[4][2];
            if (ks < 3) {
                unsigned q0, q1, q2, q3;
                ldsm4(q0, q1, q2, q3, bbase + koff[ks + 1]);
                bn[0][0] = q0; bn[0][1] = q2; bn[1][0] = q1; bn[1][1] = q3;
                ldsm4(q0, q1, q2, q3, bbase + koff[ks + 1] + 16 * ROWB);
                bn[2][0] = q0; bn[2][1] = q2; bn[3][0] = q1; bn[3][1] = q3;
            }
#pragma unroll
            for (int mt = 0; mt < 4; mt++)
#pragma unroll
                for (int nt = 0; nt < 4; nt++)
                    mma_f16(F.acc[mt][nt], a[mt], bc[nt]);
            if (ks < 3) {
#pragma unroll
                for (int nt = 0; nt < 4; nt++) {
                    bc[nt][0] = bn[nt][0]; bc[nt][1] = bn[nt][1];
                }
            }
        }
    }
}

// ---------------------------------------------------------------------------
// Fused up-GEMM: g_H[:, :3072] = { gelu(x@W1+b1) | mask*w*gelu(x@Wa) }
// ---------------------------------------------------------------------------
__global__ __launch_bounds__(256, 2)
void gemm_up(const __half* __restrict__ A, const float* __restrict__ b1,
             const int* __restrict__ idp)
{
    const int col0 = blockIdx.x * BN;
    const int row0 = blockIdx.y * BM;
    const bool moe = (col0 >= FF);
    const int idv = *idp;
    if (moe && (row0 & (SS - 1)) + BM - 1 < idv) return;   // fully masked MoE tile

    extern __shared__ __half sm[];
    const unsigned smb = (unsigned)__cvta_generic_to_shared(sm);
    const int tid = threadIdx.x, wid = tid >> 5, lane = tid & 31;
    const int m0 = (wid >> 2) * 64, n0 = (wid & 3) * 32;

    Frag F;
#pragma unroll
    for (int i = 0; i < 4; i++)
#pragma unroll
        for (int j = 0; j < 4; j++)
#pragma unroll
            for (int r = 0; r < 4; r++) F.acc[i][j][r] = 0.0f;

    gemm_core<DD, DD>(F, smb, tid, lane, m0, n0, DD / BK,
                      A + (size_t)row0 * DD, g_Wu + (size_t)col0 * DD);

    const int g = lane >> 2, t = lane & 3;
#pragma unroll
    for (int mt = 0; mt < 4; mt++) {
#pragma unroll
        for (int nt = 0; nt < 4; nt++) {
            int r0 = row0 + m0 + mt * 16 + g;
            int r1 = r0 + 8;
            int c  = col0 + n0 + nt * 8 + 2 * t;
            float v00 = F.acc[mt][nt][0], v01 = F.acc[mt][nt][1];
            float v10 = F.acc[mt][nt][2], v11 = F.acc[mt][nt][3];
            __half2 o0, o1;
            if (!moe) {
                float2 bb = *(const float2*)(b1 + c);
                o0 = { __float2half_rn(gelu_f(v00 + bb.x)), __float2half_rn(gelu_f(v01 + bb.y)) };
                o1 = { __float2half_rn(gelu_f(v10 + bb.x)), __float2half_rn(gelu_f(v11 + bb.y)) };
            } else {
                bool a0 = ((r0 & (SS - 1)) >= idv);
                bool a1 = ((r1 & (SS - 1)) >= idv);
                int e = (c - FF) >> 6;                 // 0..15
                float w0 = a0 ? g_w[r0 * 16 + e] : 0.0f;
                float w1 = a1 ? g_w[r1 * 16 + e] : 0.0f;
                o0 = { __float2half_rn(a0 ? gelu_f(v00) * w0 : 0.0f),
                       __float2half_rn(a0 ? gelu_f(v01) * w0 : 0.0f) };
                o1 = { __float2half_rn(a1 ? gelu_f(v10) * w1 : 0.0f),
                       __float2half_rn(a1 ? gelu_f(v11) * w1 : 0.0f) };
            }
            *(__half2*)(g_H + (size_t)r0 * NUP + c) = o0;
            *(__half2*)(g_H + (size_t)r1 * NUP + c) = o1;
        }
    }
}

// ---------------------------------------------------------------------------
// Fused down-GEMM: out = g_H @ [W2t;Wbt]^T + b2.
// Fully-masked row tiles use K=2048; others K=3072.
// ---------------------------------------------------------------------------
__global__ __launch_bounds__(256, 2)
void gemm_down(const float* __restrict__ b2, float* __restrict__ out,
               const int* __restrict__ idp)
{
    const int col0 = blockIdx.x * BN;
    const int row0 = blockIdx.y * BM;
    const int idv = *idp;
    const bool fully_masked = ((row0 & (SS - 1)) + BM - 1 < idv);
    const int KT = (fully_masked ? FF : NUP) / BK;

    extern __shared__ __half sm[];
    const unsigned smb = (unsigned)__cvta_generic_to_shared(sm);
    const int tid = threadIdx.x, wid = tid >> 5, lane = tid & 31;
    const int m0 = (wid >> 2) * 64, n0 = (wid & 3) * 32;

    Frag F;
#pragma unroll
    for (int i = 0; i < 4; i++)
#pragma unroll
        for (int j = 0; j < 4; j++)
#pragma unroll
            for (int r = 0; r < 4; r++) F.acc[i][j][r] = 0.0f;

    gemm_core<NUP, NUP>(F, smb, tid, lane, m0, n0, KT,
                        g_H + (size_t)row0 * NUP, g_Wd + (size_t)col0 * NUP);

    const int g = lane >> 2, t = lane & 3;
#pragma unroll
    for (int mt = 0; mt < 4; mt++) {
#pragma unroll
        for (int nt = 0; nt < 4; nt++) {
            int r0 = row0 + m0 + mt * 16 + g;
            int r1 = r0 + 8;
            int c  = col0 + n0 + nt * 8 + 2 * t;
            float2 bb = *(const float2*)(b2 + c);
            float2 o0 = { F.acc[mt][nt][0] + bb.x, F.acc[mt][nt][1] + bb.y };
            float2 o1 = { F.acc[mt][nt][2] + bb.x, F.acc[mt][nt][3] + bb.y };
            *(float2*)(out + (size_t)r0 * DD + c) = o0;
            *(float2*)(out + (size_t)r1 * DD + c) = o1;
        }
    }
}

// ---------------------------------------------------------------------------
extern "C" void kernel_launch(void* const* d_in, const int* in_sizes, int n_in,
                              void* d_out, int out_size) {
    const float* x   = (const float*)d_in[0];
    const int*   idp = (const int*)  d_in[1];
    const float* W1  = (const float*)d_in[2];
    const float* b1  = (const float*)d_in[3];
    const float* W2  = (const float*)d_in[4];
    const float* b2  = (const float*)d_in[5];
    const float* Wg1 = (const float*)d_in[6];
    const float* Wa1 = (const float*)d_in[7];
    const float* Wb1 = (const float*)d_in[8];
    const float* Wg2 = (const float*)d_in[9];
    const float* Wa2 = (const float*)d_in[10];
    const float* Wb2 = (const float*)d_in[11];
    float* out = (float*)d_out;
    (void)in_sizes; (void)n_in; (void)out_size;

    __half* Xc;
    cudaGetSymbolAddress((void**)&Xc, g_Xc);

    cudaFuncSetAttribute(gemm_up,   cudaFuncAttributeMaxDynamicSharedMemorySize, SMEM_BYTES);
    cudaFuncSetAttribute(gemm_down, cudaFuncAttributeMaxDynamicSharedMemorySize, SMEM_BYTES);

    // Prep: merged stacked repacks (one launch) + gating (emits fp16 x)
    prep_w<<<NB_WU + NB_WD, 256>>>(W1, Wa1, Wa2, W2, Wb1, Wb2);
    gate_kernel<<<TT / 32, 256>>>(x, Wg1, Wg2);

    // Fused up-projection (FFN1 + both MoE up layers)
    gemm_up<<<dim3(NUP / BN, TT / BM), 256, SMEM_BYTES>>>(Xc, b1, idp);

    // Fused down-projection (FFN2 + both MoE down layers, single out write)
    gemm_down<<<dim3(DD / BN, TT / BM), 256, SMEM_BYTES>>>(b2, out, idp);
}